// round 10
// baseline (speedup 1.0000x reference)
#include <cuda_runtime.h>
#include <math.h>

#define B_   2
#define T_   2048
#define D_   1024
#define NH_  16
#define NKV_ 4
#define HD_  64
#define KD_  256
#define KV2_ 512
#define FULLMASK 0xffffffffu

typedef unsigned long long ull;

// ---------------- f32x2 packed helpers ----------------
__device__ __forceinline__ ull ffma2(ull a, ull b, ull c) {
    ull d;
    asm("fma.rn.f32x2 %0, %1, %2, %3;" : "=l"(d) : "l"(a), "l"(b), "l"(c));
    return d;
}
__device__ __forceinline__ ull fmul2(ull a, ull b) {
    ull d;
    asm("mul.rn.f32x2 %0, %1, %2;" : "=l"(d) : "l"(a), "l"(b));
    return d;
}
__device__ __forceinline__ ull fdup2(float x) {
    ull r;
    asm("mov.b64 %0, {%1, %1};" : "=l"(r) : "f"(x));
    return r;
}
__device__ __forceinline__ void funpack2(float& lo, float& hi, ull v) {
    asm("mov.b64 {%0, %1}, %2;" : "=f"(lo), "=f"(hi) : "l"(v));
}

// ---------------- scratch (device globals; no runtime alloc) ----------------
__device__ float g_Wq_eff[D_ * D_];
__device__ float g_Wkv[KV2_ * D_];           // rows 0..255 = Wk, 256..511 = Wv_eff
__device__ float g_q[B_ * T_ * D_];
__device__ float g_kv[B_ * T_ * KV2_];
__device__ float g_qh[B_ * NH_ * T_ * HD_];  // [b][h][t][d]
__device__ float g_kh[B_ * NKV_ * T_ * HD_];
__device__ float g_vh[B_ * NKV_ * T_ * HD_];
__device__ float g_y[B_ * T_ * D_];

// ---------------- Wq_eff = Wq + Bq @ Aq ----------------
__global__ __launch_bounds__(256) void lora_fuse(
    const float* __restrict__ W, const float* __restrict__ Bm,
    const float* __restrict__ Am, float* __restrict__ Weff, int N, int K) {
    int idx = blockIdx.x * 256 + threadIdx.x;
    if (idx >= N * K) return;
    int n = idx / K, k = idx - n * K;
    float acc = W[idx];
#pragma unroll
    for (int r = 0; r < 8; r++) acc += Bm[n * 8 + r] * Am[r * K + k];
    Weff[idx] = acc;
}

// ---------------- Wkv: rows [0,256)=Wk, [256,512)=Wv + Bv@Av ----------------
__global__ __launch_bounds__(256) void build_wkv(
    const float* __restrict__ Wk, const float* __restrict__ Wv,
    const float* __restrict__ Bv, const float* __restrict__ Av,
    float* __restrict__ Wkv) {
    int idx = blockIdx.x * 256 + threadIdx.x;
    if (idx >= KV2_ * D_) return;
    int n = idx >> 10, k = idx & 1023;
    if (n < KD_) {
        Wkv[idx] = Wk[n * D_ + k];
    } else {
        int nv = n - KD_;
        float acc = Wv[nv * D_ + k];
#pragma unroll
        for (int r = 0; r < 8; r++) acc += Bv[nv * 8 + r] * Av[r * D_ + k];
        Wkv[idx] = acc;
    }
}

// ---------------- C[M,N] = A[M,K] @ B[N,K]^T, fp32 via FFMA2 ----------------
__global__ __launch_bounds__(256, 2) void gemm_nt_f2(
    const float* __restrict__ A, const float* __restrict__ B,
    float* __restrict__ C, int M, int N, int K) {
    __shared__ float As[16 * 128];  // [kk][m]
    __shared__ float Bs[16 * 128];  // [kk][n]
    int tid = threadIdx.x;
    int tx = tid & 15, ty = tid >> 4;
    const float* Ab = A + (size_t)(blockIdx.y * 128) * K;
    const float* Bb = B + (size_t)(blockIdx.x * 128) * K;
    int lr = tid >> 2;            // 0..63
    int lc = (tid & 3) << 2;      // 0,4,8,12

    ull acc[8][4];
#pragma unroll
    for (int i = 0; i < 8; i++)
#pragma unroll
        for (int j = 0; j < 4; j++) acc[i][j] = 0ull;

    float4 av0 = *reinterpret_cast<const float4*>(Ab + (size_t)lr * K + lc);
    float4 av1 = *reinterpret_cast<const float4*>(Ab + (size_t)(lr + 64) * K + lc);
    float4 bv0 = *reinterpret_cast<const float4*>(Bb + (size_t)lr * K + lc);
    float4 bv1 = *reinterpret_cast<const float4*>(Bb + (size_t)(lr + 64) * K + lc);

    for (int k0 = 0; k0 < K; k0 += 16) {
        __syncthreads();
        {
            float a0[4] = {av0.x, av0.y, av0.z, av0.w};
            float a1[4] = {av1.x, av1.y, av1.z, av1.w};
            float b0[4] = {bv0.x, bv0.y, bv0.z, bv0.w};
            float b1[4] = {bv1.x, bv1.y, bv1.z, bv1.w};
#pragma unroll
            for (int c = 0; c < 4; c++) {
                As[(lc + c) * 128 + lr]      = a0[c];
                As[(lc + c) * 128 + lr + 64] = a1[c];
                Bs[(lc + c) * 128 + lr]      = b0[c];
                Bs[(lc + c) * 128 + lr + 64] = b1[c];
            }
        }
        __syncthreads();
        if (k0 + 16 < K) {
            av0 = *reinterpret_cast<const float4*>(Ab + (size_t)lr * K + k0 + 16 + lc);
            av1 = *reinterpret_cast<const float4*>(Ab + (size_t)(lr + 64) * K + k0 + 16 + lc);
            bv0 = *reinterpret_cast<const float4*>(Bb + (size_t)lr * K + k0 + 16 + lc);
            bv1 = *reinterpret_cast<const float4*>(Bb + (size_t)(lr + 64) * K + k0 + 16 + lc);
        }
#pragma unroll
        for (int kk = 0; kk < 16; kk++) {
            float4 a0 = *reinterpret_cast<const float4*>(&As[kk * 128 + ty * 4]);
            float4 a1 = *reinterpret_cast<const float4*>(&As[kk * 128 + 64 + ty * 4]);
            ulonglong2 b0 = *reinterpret_cast<const ulonglong2*>(&Bs[kk * 128 + tx * 4]);
            ulonglong2 b1 = *reinterpret_cast<const ulonglong2*>(&Bs[kk * 128 + 64 + tx * 4]);
            ull bb[4] = {b0.x, b0.y, b1.x, b1.y};
            float av[8] = {a0.x, a0.y, a0.z, a0.w, a1.x, a1.y, a1.z, a1.w};
#pragma unroll
            for (int i = 0; i < 8; i++) {
                ull ai = fdup2(av[i]);
#pragma unroll
                for (int j = 0; j < 4; j++) acc[i][j] = ffma2(ai, bb[j], acc[i][j]);
            }
        }
    }

#pragma unroll
    for (int i = 0; i < 8; i++) {
        int rloc = (i < 4) ? (ty * 4 + i) : (64 + ty * 4 + i - 4);
        size_t row = (size_t)blockIdx.y * 128 + rloc;
        float c0, c1, c2, c3, c4, c5, c6, c7;
        funpack2(c0, c1, acc[i][0]);
        funpack2(c2, c3, acc[i][1]);
        funpack2(c4, c5, acc[i][2]);
        funpack2(c6, c7, acc[i][3]);
        float* Cp = C + row * N + blockIdx.x * 128;
        *reinterpret_cast<float4*>(Cp + tx * 4)      = make_float4(c0, c1, c2, c3);
        *reinterpret_cast<float4*>(Cp + 64 + tx * 4) = make_float4(c4, c5, c6, c7);
    }
}

// ---------------- RoPE helpers ----------------
__device__ __forceinline__ void rope_cs(int t, int j, float& c, float& s) {
    float e = (2.0f * (float)j) / 16.0f;
    float inv = 1.0f / powf(10000.0f, e);
    float f = (float)t * inv;
    c = cosf(f);
    s = sinf(f);
}

__device__ __forceinline__ void norm_rope_row(
    const float* __restrict__ src, float* __restrict__ dst,
    int t, float scale, int lane) {
    float2 v = *reinterpret_cast<const float2*>(src + lane * 2);
    float ss = v.x * v.x + v.y * v.y;
#pragma unroll
    for (int o = 16; o; o >>= 1) ss += __shfl_xor_sync(FULLMASK, ss, o);
    float rms = rsqrtf(ss * (1.0f / 64.0f) + 1.1920929e-7f);
    float v0 = v.x * rms, v1 = v.y * rms;
    float u0 = __shfl_xor_sync(FULLMASK, v0, 4);
    float u1 = __shfl_xor_sync(FULLMASK, v1, 4);
    int d0 = lane * 2;
    if (d0 < 8) {
        float c0, s0, c1, s1;
        rope_cs(t, d0, c0, s0);
        rope_cs(t, d0 + 1, c1, s1);
        v0 = v0 * c0 + u0 * s0;
        v1 = v1 * c1 + u1 * s1;
    } else if (d0 < 16) {
        float c0, s0, c1, s1;
        rope_cs(t, d0 - 8, c0, s0);
        rope_cs(t, d0 - 7, c1, s1);
        v0 = -v0 * c0 + u0 * s0;
        v1 = -v1 * c1 + u1 * s1;
    }
    *reinterpret_cast<float2*>(dst + lane * 2) = make_float2(v0 * scale, v1 * scale);
}

__global__ __launch_bounds__(256) void q_prep(
    const float* __restrict__ Qin, const float* __restrict__ qgain,
    float* __restrict__ Qout) {
    int warp = (blockIdx.x * 256 + threadIdx.x) >> 5;
    int lane = threadIdx.x & 31;
    if (warp >= B_ * T_ * NH_) return;
    int h = warp & 15;
    int t = (warp >> 4) & 2047;
    int b = warp >> 15;
    const float* src = Qin + ((size_t)(b * T_ + t)) * D_ + h * HD_;
    float* dst = Qout + (((size_t)(b * NH_ + h)) * T_ + t) * HD_;
    float scale = qgain[h] * 0.125f;
    norm_rope_row(src, dst, t, scale, lane);
}

__global__ __launch_bounds__(256) void kv_prep(
    const float* __restrict__ KVin,
    float* __restrict__ Kout, float* __restrict__ Vout) {
    int warp = (blockIdx.x * 256 + threadIdx.x) >> 5;
    int lane = threadIdx.x & 31;
    if (warp >= B_ * T_ * NKV_) return;
    int hk = warp & 3;
    int t = (warp >> 2) & 2047;
    int b = warp >> 13;
    const float* ksrc = KVin + ((size_t)(b * T_ + t)) * KV2_ + hk * HD_;
    float* kdst = Kout + (((size_t)(b * NKV_ + hk)) * T_ + t) * HD_;
    norm_rope_row(ksrc, kdst, t, 1.0f, lane);
    const float* vsrc = KVin + ((size_t)(b * T_ + t)) * KV2_ + KD_ + hk * HD_;
    float* vdst = Vout + (((size_t)(b * NKV_ + hk)) * T_ + t) * HD_;
    *reinterpret_cast<float2*>(vdst + lane * 2) =
        *reinterpret_cast<const float2*>(vsrc + lane * 2);
}

// ---------------- causal flash attention v2, fp32 via FFMA2 ----------------
// BM=128 q-rows x BN=64 k-cols, 256 threads: tx=tid&7 (8 cols of 8),
// ty=tid>>3 (32 row-groups of 4). Per-thread microtile 4 rows x 8 cols.
// smem: Qs[d][r] stride 132 | Ks[d][c] stride 68 | Vs[j][d] stride 64 |
//       Ps[r][j] stride 68.  Total 102400B -> 2 CTAs/SM (16 warps).
#define QSTR 132
#define KSTR 68
#define PSTR 68
#define SM_QS 0
#define SM_KS 33792
#define SM_VS 51200
#define SM_PS 67584
#define SM_TOT 102400
__global__ __launch_bounds__(256, 2) void attn_f2(
    const float* __restrict__ Qh, const float* __restrict__ Kh,
    const float* __restrict__ Vh, float* __restrict__ Y) {
    extern __shared__ char smraw[];
    float* Qs = reinterpret_cast<float*>(smraw + SM_QS);
    float* Ks = reinterpret_cast<float*>(smraw + SM_KS);
    float* Vs = reinterpret_cast<float*>(smraw + SM_VS);
    float* Ps = reinterpret_cast<float*>(smraw + SM_PS);
    int tid = threadIdx.x;
    int tx = tid & 7, ty = tid >> 3;      // tx 0..7, ty 0..31
    int bh = blockIdx.y;
    int b = bh >> 4, h = bh & 15;
    int qt = (int)gridDim.x - 1 - (int)blockIdx.x;   // reversed for balance
    int i0 = qt * 128;
    int kvh = h >> 2;
    const float* Qg = Qh + (((size_t)(b * NH_ + h)) * T_ + i0) * HD_;
    const float* Kg = Kh + ((size_t)(b * NKV_ + kvh)) * T_ * HD_;
    const float* Vg = Vh + ((size_t)(b * NKV_ + kvh)) * T_ * HD_;

    // load Q tile (128 rows x 64 d) transposed into Qs[d][r]
#pragma unroll
    for (int tl = 0; tl < 8; tl++) {
        int idx = tid + tl * 256;             // float4 index 0..2047
        int r = idx >> 4, d4 = (idx & 15) << 2;
        float4 q4 = *reinterpret_cast<const float4*>(Qg + r * 64 + d4);
        Qs[(d4 + 0) * QSTR + r] = q4.x; Qs[(d4 + 1) * QSTR + r] = q4.y;
        Qs[(d4 + 2) * QSTR + r] = q4.z; Qs[(d4 + 3) * QSTR + r] = q4.w;
    }

    float m[4], l[4];
    ull acc2[4][4];   // [row i][d-pair]
#pragma unroll
    for (int i = 0; i < 4; i++) {
        m[i] = -1e30f; l[i] = 0.f;
#pragma unroll
        for (int dp = 0; dp < 4; dp++) acc2[i][dp] = 0ull;
    }

    int ntiles = qt * 2 + 2;   // cover cols up to i0+127
    for (int kt = 0; kt < ntiles; kt++) {
        int j0 = kt * 64;
        __syncthreads();  // smem safe to overwrite; covers Q visibility on iter 0
        // load K (transposed, Ks[d][c]) and V (natural, Vs[j][d])
#pragma unroll
        for (int tl = 0; tl < 4; tl++) {
            int idx = tid + tl * 256;          // float4 index 0..1023
            int c = idx >> 4, d4 = (idx & 15) << 2;
            float4 k4 = *reinterpret_cast<const float4*>(Kg + (j0 + c) * 64 + d4);
            Ks[(d4 + 0) * KSTR + c] = k4.x; Ks[(d4 + 1) * KSTR + c] = k4.y;
            Ks[(d4 + 2) * KSTR + c] = k4.z; Ks[(d4 + 3) * KSTR + c] = k4.w;
            *reinterpret_cast<float4*>(Vs + idx * 4) =
                *reinterpret_cast<const float4*>(Vg + j0 * 64 + idx * 4);
        }
        __syncthreads();

        // S = Q K^T : s2[i][cp] = cols (tx*8+2cp, +1) for row ty*4+i
        ull s2[4][4];
#pragma unroll
        for (int i = 0; i < 4; i++)
#pragma unroll
            for (int cp = 0; cp < 4; cp++) s2[i][cp] = 0ull;
#pragma unroll 8
        for (int d = 0; d < 64; d++) {
            float4 qv = *reinterpret_cast<const float4*>(&Qs[d * QSTR + ty * 4]);
            ulonglong2 kA = *reinterpret_cast<const ulonglong2*>(&Ks[d * KSTR + tx * 8]);
            ulonglong2 kB = *reinterpret_cast<const ulonglong2*>(&Ks[d * KSTR + tx * 8 + 4]);
            ull kk[4] = {kA.x, kA.y, kB.x, kB.y};
            float qq[4] = {qv.x, qv.y, qv.z, qv.w};
#pragma unroll
            for (int i = 0; i < 4; i++) {
                ull qi = fdup2(qq[i]);
#pragma unroll
                for (int cp = 0; cp < 4; cp++)
                    s2[i][cp] = ffma2(qi, kk[cp], s2[i][cp]);
            }
        }
        float s[4][8];
#pragma unroll
        for (int i = 0; i < 4; i++)
#pragma unroll
            for (int cp = 0; cp < 4; cp++)
                funpack2(s[i][2 * cp], s[i][2 * cp + 1], s2[i][cp]);

        if (kt >= ntiles - 2) {  // diagonal region: mask col > row
#pragma unroll
            for (int i = 0; i < 4; i++) {
                int rg = i0 + ty * 4 + i;
#pragma unroll
                for (int j = 0; j < 8; j++)
                    if (j0 + tx * 8 + j > rg) s[i][j] = -1e30f;
            }
        }

        // online softmax (row reduce over the 8 tx lanes: xor 1,2,4)
#pragma unroll
        for (int i = 0; i < 4; i++) {
            float tmax = s[i][0];
#pragma unroll
            for (int j = 1; j < 8; j++) tmax = fmaxf(tmax, s[i][j]);
#pragma unroll
            for (int o = 4; o; o >>= 1)
                tmax = fmaxf(tmax, __shfl_xor_sync(FULLMASK, tmax, o));
            float mn = fmaxf(m[i], tmax);
            float sf = __expf(m[i] - mn);
            m[i] = mn;
            float r = 0.f;
#pragma unroll
            for (int j = 0; j < 8; j++) {
                float p = __expf(s[i][j] - mn);
                s[i][j] = p;
                r += p;
            }
#pragma unroll
            for (int o = 4; o; o >>= 1) r += __shfl_xor_sync(FULLMASK, r, o);
            l[i] = l[i] * sf + r;
            ull sfd = fdup2(sf);
#pragma unroll
            for (int dp = 0; dp < 4; dp++) acc2[i][dp] = fmul2(acc2[i][dp], sfd);
            int rl = ty * 4 + i;
            *reinterpret_cast<float4*>(&Ps[rl * PSTR + tx * 8]) =
                make_float4(s[i][0], s[i][1], s[i][2], s[i][3]);
            *reinterpret_cast<float4*>(&Ps[rl * PSTR + tx * 8 + 4]) =
                make_float4(s[i][4], s[i][5], s[i][6], s[i][7]);
        }
        __syncwarp();   // P rows ty*4+i are produced by this warp's 8 tx lanes only

        // acc += P @ V : V d-pairs natural, P scalars dup'd in regs
#pragma unroll 4
        for (int jj2 = 0; jj2 < 32; jj2++) {
            int j = jj2 * 2;
            ulonglong2 vaA = *reinterpret_cast<const ulonglong2*>(&Vs[j * 64 + tx * 8]);
            ulonglong2 vaB = *reinterpret_cast<const ulonglong2*>(&Vs[j * 64 + tx * 8 + 4]);
            ulonglong2 vbA = *reinterpret_cast<const ulonglong2*>(&Vs[(j + 1) * 64 + tx * 8]);
            ulonglong2 vbB = *reinterpret_cast<const ulonglong2*>(&Vs[(j + 1) * 64 + tx * 8 + 4]);
            ull va[4] = {vaA.x, vaA.y, vaB.x, vaB.y};
            ull vb[4] = {vbA.x, vbA.y, vbB.x, vbB.y};
#pragma unroll
            for (int i = 0; i < 4; i++) {
                float2 pp = *reinterpret_cast<const float2*>(&Ps[(ty * 4 + i) * PSTR + j]);
                ull pa = fdup2(pp.x);
                ull pb = fdup2(pp.y);
#pragma unroll
                for (int dp = 0; dp < 4; dp++) {
                    acc2[i][dp] = ffma2(pa, va[dp], acc2[i][dp]);
                    acc2[i][dp] = ffma2(pb, vb[dp], acc2[i][dp]);
                }
            }
        }
    }

    // epilogue: normalize, write y[b][t][h*64 + d]
#pragma unroll
    for (int i = 0; i < 4; i++) {
        float inv_l = 1.0f / l[i];
        int row = i0 + ty * 4 + i;
        float a0, a1, a2, a3, a4, a5, a6, a7;
        funpack2(a0, a1, acc2[i][0]);
        funpack2(a2, a3, acc2[i][1]);
        funpack2(a4, a5, acc2[i][2]);
        funpack2(a6, a7, acc2[i][3]);
        float* Yp = Y + ((size_t)b * T_ + row) * D_ + h * HD_ + tx * 8;
        *reinterpret_cast<float4*>(Yp) =
            make_float4(a0 * inv_l, a1 * inv_l, a2 * inv_l, a3 * inv_l);
        *reinterpret_cast<float4*>(Yp + 4) =
            make_float4(a4 * inv_l, a5 * inv_l, a6 * inv_l, a7 * inv_l);
    }
}

// ---------------- launch ----------------
extern "C" void kernel_launch(void* const* d_in, const int* in_sizes, int n_in,
                              void* d_out, int out_size) {
    const float* x     = (const float*)d_in[0];
    const float* Wq    = (const float*)d_in[1];
    const float* Wk    = (const float*)d_in[2];
    const float* Wv    = (const float*)d_in[3];
    const float* Wproj = (const float*)d_in[4];
    const float* qg    = (const float*)d_in[5];
    const float* Aq    = (const float*)d_in[6];
    const float* Bq    = (const float*)d_in[7];
    const float* Av    = (const float*)d_in[8];
    const float* Bv    = (const float*)d_in[9];
    float* out = (float*)d_out;

    float *pWqe, *pWkv, *pq, *pkv, *pqh, *pkh, *pvh, *py;
    cudaGetSymbolAddress((void**)&pWqe, g_Wq_eff);
    cudaGetSymbolAddress((void**)&pWkv, g_Wkv);
    cudaGetSymbolAddress((void**)&pq, g_q);
    cudaGetSymbolAddress((void**)&pkv, g_kv);
    cudaGetSymbolAddress((void**)&pqh, g_qh);
    cudaGetSymbolAddress((void**)&pkh, g_kh);
    cudaGetSymbolAddress((void**)&pvh, g_vh);
    cudaGetSymbolAddress((void**)&py, g_y);

    // 1. fold LoRA / build combined weights
    lora_fuse<<<(D_ * D_) / 256, 256>>>(Wq, Bq, Aq, pWqe, D_, D_);
    build_wkv<<<(KV2_ * D_) / 256, 256>>>(Wk, Wv, Bv, Av, pWkv);

    // 2. projections (FFMA2 GEMM)
    dim3 gq(D_ / 128, (B_ * T_) / 128);
    dim3 gkv(KV2_ / 128, (B_ * T_) / 128);
    gemm_nt_f2<<<gq, 256>>>(x, pWqe, pq, B_ * T_, D_, D_);
    gemm_nt_f2<<<gkv, 256>>>(x, pWkv, pkv, B_ * T_, KV2_, D_);

    // 3. norm + rope + transpose
    q_prep<<<(B_ * T_ * NH_) / 8, 256>>>(pq, qg, pqh);
    kv_prep<<<(B_ * T_ * NKV_) / 8, 256>>>(pkv, pkh, pvh);

    // 4. attention (FFMA2 flash v2: BM=128, 16 warps/SM)
    cudaFuncSetAttribute(attn_f2,
                         cudaFuncAttributeMaxDynamicSharedMemorySize, SM_TOT);
    dim3 ga(T_ / 128, B_ * NH_);
    attn_f2<<<ga, 256, SM_TOT>>>(pqh, pkh, pvh, py);

    // 5. output projection
    gemm_nt_f2<<<gq, 256>>>(py, Wproj, out, B_ * T_, D_, D_);
}

// round 11
// speedup vs baseline: 1.0704x; 1.0704x over previous
#include <cuda_runtime.h>
#include <math.h>

#define B_   2
#define T_   2048
#define D_   1024
#define NH_  16
#define NKV_ 4
#define HD_  64
#define KD_  256
#define KV2_ 512
#define FULLMASK 0xffffffffu

typedef unsigned long long ull;

// ---------------- f32x2 packed helpers ----------------
__device__ __forceinline__ ull ffma2(ull a, ull b, ull c) {
    ull d;
    asm("fma.rn.f32x2 %0, %1, %2, %3;" : "=l"(d) : "l"(a), "l"(b), "l"(c));
    return d;
}
__device__ __forceinline__ ull fmul2(ull a, ull b) {
    ull d;
    asm("mul.rn.f32x2 %0, %1, %2;" : "=l"(d) : "l"(a), "l"(b));
    return d;
}
__device__ __forceinline__ ull fdup2(float x) {
    ull r;
    asm("mov.b64 %0, {%1, %1};" : "=l"(r) : "f"(x));
    return r;
}
__device__ __forceinline__ void funpack2(float& lo, float& hi, ull v) {
    asm("mov.b64 {%0, %1}, %2;" : "=f"(lo), "=f"(hi) : "l"(v));
}

// ---------------- scratch (device globals; no runtime alloc) ----------------
__device__ float g_Wq_eff[D_ * D_];
__device__ float g_Wkv[KV2_ * D_];           // rows 0..255 = Wk, 256..511 = Wv_eff
__device__ float g_q[B_ * T_ * D_];
__device__ float g_kv[B_ * T_ * KV2_];
__device__ float g_qh[B_ * NH_ * T_ * HD_];  // [b][h][t][d]
__device__ float g_kh[B_ * NKV_ * T_ * HD_];
__device__ float g_vh[B_ * NKV_ * T_ * HD_];
__device__ float g_y[B_ * T_ * D_];

// ---------------- Wq_eff = Wq + Bq @ Aq ----------------
__global__ __launch_bounds__(256) void lora_fuse(
    const float* __restrict__ W, const float* __restrict__ Bm,
    const float* __restrict__ Am, float* __restrict__ Weff, int N, int K) {
    int idx = blockIdx.x * 256 + threadIdx.x;
    if (idx >= N * K) return;
    int n = idx / K, k = idx - n * K;
    float acc = W[idx];
#pragma unroll
    for (int r = 0; r < 8; r++) acc += Bm[n * 8 + r] * Am[r * K + k];
    Weff[idx] = acc;
}

// ---------------- Wkv: rows [0,256)=Wk, [256,512)=Wv + Bv@Av ----------------
__global__ __launch_bounds__(256) void build_wkv(
    const float* __restrict__ Wk, const float* __restrict__ Wv,
    const float* __restrict__ Bv, const float* __restrict__ Av,
    float* __restrict__ Wkv) {
    int idx = blockIdx.x * 256 + threadIdx.x;
    if (idx >= KV2_ * D_) return;
    int n = idx >> 10, k = idx & 1023;
    if (n < KD_) {
        Wkv[idx] = Wk[n * D_ + k];
    } else {
        int nv = n - KD_;
        float acc = Wv[nv * D_ + k];
#pragma unroll
        for (int r = 0; r < 8; r++) acc += Bv[nv * 8 + r] * Av[r * D_ + k];
        Wkv[idx] = acc;
    }
}

// ---------------- C[M,N] = A[M,K] @ B[N,K]^T, fp32 via FFMA2 ----------------
__global__ __launch_bounds__(256, 2) void gemm_nt_f2(
    const float* __restrict__ A, const float* __restrict__ B,
    float* __restrict__ C, int M, int N, int K) {
    __shared__ float As[16 * 128];  // [kk][m]
    __shared__ float Bs[16 * 128];  // [kk][n]
    int tid = threadIdx.x;
    int tx = tid & 15, ty = tid >> 4;
    const float* Ab = A + (size_t)(blockIdx.y * 128) * K;
    const float* Bb = B + (size_t)(blockIdx.x * 128) * K;
    int lr = tid >> 2;            // 0..63
    int lc = (tid & 3) << 2;      // 0,4,8,12

    ull acc[8][4];
#pragma unroll
    for (int i = 0; i < 8; i++)
#pragma unroll
        for (int j = 0; j < 4; j++) acc[i][j] = 0ull;

    float4 av0 = *reinterpret_cast<const float4*>(Ab + (size_t)lr * K + lc);
    float4 av1 = *reinterpret_cast<const float4*>(Ab + (size_t)(lr + 64) * K + lc);
    float4 bv0 = *reinterpret_cast<const float4*>(Bb + (size_t)lr * K + lc);
    float4 bv1 = *reinterpret_cast<const float4*>(Bb + (size_t)(lr + 64) * K + lc);

    for (int k0 = 0; k0 < K; k0 += 16) {
        __syncthreads();
        {
            float a0[4] = {av0.x, av0.y, av0.z, av0.w};
            float a1[4] = {av1.x, av1.y, av1.z, av1.w};
            float b0[4] = {bv0.x, bv0.y, bv0.z, bv0.w};
            float b1[4] = {bv1.x, bv1.y, bv1.z, bv1.w};
#pragma unroll
            for (int c = 0; c < 4; c++) {
                As[(lc + c) * 128 + lr]      = a0[c];
                As[(lc + c) * 128 + lr + 64] = a1[c];
                Bs[(lc + c) * 128 + lr]      = b0[c];
                Bs[(lc + c) * 128 + lr + 64] = b1[c];
            }
        }
        __syncthreads();
        if (k0 + 16 < K) {
            av0 = *reinterpret_cast<const float4*>(Ab + (size_t)lr * K + k0 + 16 + lc);
            av1 = *reinterpret_cast<const float4*>(Ab + (size_t)(lr + 64) * K + k0 + 16 + lc);
            bv0 = *reinterpret_cast<const float4*>(Bb + (size_t)lr * K + k0 + 16 + lc);
            bv1 = *reinterpret_cast<const float4*>(Bb + (size_t)(lr + 64) * K + k0 + 16 + lc);
        }
#pragma unroll
        for (int kk = 0; kk < 16; kk++) {
            float4 a0 = *reinterpret_cast<const float4*>(&As[kk * 128 + ty * 4]);
            float4 a1 = *reinterpret_cast<const float4*>(&As[kk * 128 + 64 + ty * 4]);
            ulonglong2 b0 = *reinterpret_cast<const ulonglong2*>(&Bs[kk * 128 + tx * 4]);
            ulonglong2 b1 = *reinterpret_cast<const ulonglong2*>(&Bs[kk * 128 + 64 + tx * 4]);
            ull bb[4] = {b0.x, b0.y, b1.x, b1.y};
            float av[8] = {a0.x, a0.y, a0.z, a0.w, a1.x, a1.y, a1.z, a1.w};
#pragma unroll
            for (int i = 0; i < 8; i++) {
                ull ai = fdup2(av[i]);
#pragma unroll
                for (int j = 0; j < 4; j++) acc[i][j] = ffma2(ai, bb[j], acc[i][j]);
            }
        }
    }

#pragma unroll
    for (int i = 0; i < 8; i++) {
        int rloc = (i < 4) ? (ty * 4 + i) : (64 + ty * 4 + i - 4);
        size_t row = (size_t)blockIdx.y * 128 + rloc;
        float c0, c1, c2, c3, c4, c5, c6, c7;
        funpack2(c0, c1, acc[i][0]);
        funpack2(c2, c3, acc[i][1]);
        funpack2(c4, c5, acc[i][2]);
        funpack2(c6, c7, acc[i][3]);
        float* Cp = C + row * N + blockIdx.x * 128;
        *reinterpret_cast<float4*>(Cp + tx * 4)      = make_float4(c0, c1, c2, c3);
        *reinterpret_cast<float4*>(Cp + 64 + tx * 4) = make_float4(c4, c5, c6, c7);
    }
}

// ---------------- RoPE helpers ----------------
__device__ __forceinline__ void rope_cs(int t, int j, float& c, float& s) {
    float e = (2.0f * (float)j) / 16.0f;
    float inv = 1.0f / powf(10000.0f, e);
    float f = (float)t * inv;
    c = cosf(f);
    s = sinf(f);
}

__device__ __forceinline__ void norm_rope_row(
    const float* __restrict__ src, float* __restrict__ dst,
    int t, float scale, int lane) {
    float2 v = *reinterpret_cast<const float2*>(src + lane * 2);
    float ss = v.x * v.x + v.y * v.y;
#pragma unroll
    for (int o = 16; o; o >>= 1) ss += __shfl_xor_sync(FULLMASK, ss, o);
    float rms = rsqrtf(ss * (1.0f / 64.0f) + 1.1920929e-7f);
    float v0 = v.x * rms, v1 = v.y * rms;
    float u0 = __shfl_xor_sync(FULLMASK, v0, 4);
    float u1 = __shfl_xor_sync(FULLMASK, v1, 4);
    int d0 = lane * 2;
    if (d0 < 8) {
        float c0, s0, c1, s1;
        rope_cs(t, d0, c0, s0);
        rope_cs(t, d0 + 1, c1, s1);
        v0 = v0 * c0 + u0 * s0;
        v1 = v1 * c1 + u1 * s1;
    } else if (d0 < 16) {
        float c0, s0, c1, s1;
        rope_cs(t, d0 - 8, c0, s0);
        rope_cs(t, d0 - 7, c1, s1);
        v0 = -v0 * c0 + u0 * s0;
        v1 = -v1 * c1 + u1 * s1;
    }
    *reinterpret_cast<float2*>(dst + lane * 2) = make_float2(v0 * scale, v1 * scale);
}

__global__ __launch_bounds__(256) void q_prep(
    const float* __restrict__ Qin, const float* __restrict__ qgain,
    float* __restrict__ Qout) {
    int warp = (blockIdx.x * 256 + threadIdx.x) >> 5;
    int lane = threadIdx.x & 31;
    if (warp >= B_ * T_ * NH_) return;
    int h = warp & 15;
    int t = (warp >> 4) & 2047;
    int b = warp >> 15;
    const float* src = Qin + ((size_t)(b * T_ + t)) * D_ + h * HD_;
    float* dst = Qout + (((size_t)(b * NH_ + h)) * T_ + t) * HD_;
    float scale = qgain[h] * 0.125f;
    norm_rope_row(src, dst, t, scale, lane);
}

__global__ __launch_bounds__(256) void kv_prep(
    const float* __restrict__ KVin,
    float* __restrict__ Kout, float* __restrict__ Vout) {
    int warp = (blockIdx.x * 256 + threadIdx.x) >> 5;
    int lane = threadIdx.x & 31;
    if (warp >= B_ * T_ * NKV_) return;
    int hk = warp & 3;
    int t = (warp >> 2) & 2047;
    int b = warp >> 13;
    const float* ksrc = KVin + ((size_t)(b * T_ + t)) * KV2_ + hk * HD_;
    float* kdst = Kout + (((size_t)(b * NKV_ + hk)) * T_ + t) * HD_;
    norm_rope_row(ksrc, kdst, t, 1.0f, lane);
    const float* vsrc = KVin + ((size_t)(b * T_ + t)) * KV2_ + KD_ + hk * HD_;
    float* vdst = Vout + (((size_t)(b * NKV_ + hk)) * T_ + t) * HD_;
    *reinterpret_cast<float2*>(vdst + lane * 2) =
        *reinterpret_cast<const float2*>(vsrc + lane * 2);
}

// ---------------- causal flash attention v3, fp32 via FFMA2 ----------------
// 64q x 64k tile, 128 threads: tx=tid&7 (8 d/col-groups of 8), ty=tid>>3
// (16 row-groups of 4). Per-thread microtile 4 rows x 8 cols.
// smem: Qs[d][r] stride 68 | Ks[d][c] stride 68 | Vs[j][d] 64 | Ps[r][j] stride 68
// = 68608B -> 3 CTAs/SM (12 warps).
#define ASTR 68
#define AQ_OFF 0
#define AK_OFF (64 * ASTR)
#define AV_OFF (2 * 64 * ASTR)
#define AP_OFF (2 * 64 * ASTR + 4096)
#define A_SMEM ((2 * 64 * ASTR + 4096 + 64 * ASTR) * 4)
__global__ __launch_bounds__(128, 3) void attn_f3(
    const float* __restrict__ Qh, const float* __restrict__ Kh,
    const float* __restrict__ Vh, float* __restrict__ Y) {
    extern __shared__ float sm[];
    float* Qs = sm + AQ_OFF;
    float* Ks = sm + AK_OFF;
    float* Vs = sm + AV_OFF;
    float* Ps = sm + AP_OFF;
    int tid = threadIdx.x;
    int tx = tid & 7, ty = tid >> 3;     // tx 0..7 (cols), ty 0..15 (rows)
    int bh = blockIdx.y;
    int b = bh >> 4, h = bh & 15;
    int qt = (int)gridDim.x - 1 - (int)blockIdx.x;  // reversed for balance
    int i0 = qt * 64;
    int kvh = h >> 2;
    const float* Qg = Qh + (((size_t)(b * NH_ + h)) * T_ + i0) * HD_;
    const float* Kg = Kh + ((size_t)(b * NKV_ + kvh)) * T_ * HD_;
    const float* Vg = Vh + ((size_t)(b * NKV_ + kvh)) * T_ * HD_;

    // load Q tile transposed: Qs[d][r]
#pragma unroll
    for (int tl = 0; tl < 8; tl++) {
        int idx = tid + tl * 128;            // float4 index 0..1023
        int r = idx >> 4, d4 = (idx & 15) << 2;
        float4 q4 = *reinterpret_cast<const float4*>(Qg + r * 64 + d4);
        Qs[(d4 + 0) * ASTR + r] = q4.x; Qs[(d4 + 1) * ASTR + r] = q4.y;
        Qs[(d4 + 2) * ASTR + r] = q4.z; Qs[(d4 + 3) * ASTR + r] = q4.w;
    }

    float m[4], l[4];
    ull acc2[4][4];   // [row i][d-pair dp]: d = tx*8 + 2dp, +1
#pragma unroll
    for (int i = 0; i < 4; i++) {
        m[i] = -1e30f; l[i] = 0.f;
#pragma unroll
        for (int dp = 0; dp < 4; dp++) acc2[i][dp] = 0ull;
    }

    int ntiles = qt + 1;
    for (int kt = 0; kt < ntiles; kt++) {
        int j0 = kt * 64;
        __syncthreads();   // smem reusable; also covers Q visibility on iter 0
        // load K transposed (Ks[d][c]) and V natural (Vs[j][d])
#pragma unroll
        for (int tl = 0; tl < 8; tl++) {
            int idx = tid + tl * 128;
            int c = idx >> 4, d4 = (idx & 15) << 2;
            float4 k4 = *reinterpret_cast<const float4*>(Kg + (j0 + c) * 64 + d4);
            Ks[(d4 + 0) * ASTR + c] = k4.x; Ks[(d4 + 1) * ASTR + c] = k4.y;
            Ks[(d4 + 2) * ASTR + c] = k4.z; Ks[(d4 + 3) * ASTR + c] = k4.w;
            *reinterpret_cast<float4*>(Vs + idx * 4) =
                *reinterpret_cast<const float4*>(Vg + j0 * 64 + idx * 4);
        }
        __syncthreads();

        // S = Q K^T : s2[i][cp] = cols (tx*8+2cp, +1), row ty*4+i
        ull s2[4][4];
#pragma unroll
        for (int i = 0; i < 4; i++)
#pragma unroll
            for (int cp = 0; cp < 4; cp++) s2[i][cp] = 0ull;
#pragma unroll 8
        for (int d = 0; d < 64; d++) {
            float4 qv = *reinterpret_cast<const float4*>(&Qs[d * ASTR + ty * 4]);
            ulonglong2 kA = *reinterpret_cast<const ulonglong2*>(&Ks[d * ASTR + tx * 8]);
            ulonglong2 kB = *reinterpret_cast<const ulonglong2*>(&Ks[d * ASTR + tx * 8 + 4]);
            ull kk[4] = {kA.x, kA.y, kB.x, kB.y};
            float qq[4] = {qv.x, qv.y, qv.z, qv.w};
#pragma unroll
            for (int i = 0; i < 4; i++) {
                ull qi = fdup2(qq[i]);
#pragma unroll
                for (int cp = 0; cp < 4; cp++)
                    s2[i][cp] = ffma2(qi, kk[cp], s2[i][cp]);
            }
        }
        float s[4][8];
#pragma unroll
        for (int i = 0; i < 4; i++)
#pragma unroll
            for (int cp = 0; cp < 4; cp++)
                funpack2(s[i][2 * cp], s[i][2 * cp + 1], s2[i][cp]);

        if (kt == ntiles - 1) {  // diagonal tile: mask col > row
#pragma unroll
            for (int i = 0; i < 4; i++) {
                int rl = ty * 4 + i;
#pragma unroll
                for (int j = 0; j < 8; j++)
                    if (tx * 8 + j > rl) s[i][j] = -1e30f;
            }
        }

        // online softmax; row spread over the 8 tx lanes (bits 0..2 -> xor 1,2,4)
#pragma unroll
        for (int i = 0; i < 4; i++) {
            float tmax = s[i][0];
#pragma unroll
            for (int j = 1; j < 8; j++) tmax = fmaxf(tmax, s[i][j]);
#pragma unroll
            for (int o = 4; o; o >>= 1)
                tmax = fmaxf(tmax, __shfl_xor_sync(FULLMASK, tmax, o));
            float mn = fmaxf(m[i], tmax);
            float sf = __expf(m[i] - mn);
            m[i] = mn;
            float r = 0.f;
#pragma unroll
            for (int j = 0; j < 8; j++) {
                float p = __expf(s[i][j] - mn);
                s[i][j] = p;
                r += p;
            }
#pragma unroll
            for (int o = 4; o; o >>= 1) r += __shfl_xor_sync(FULLMASK, r, o);
            l[i] = l[i] * sf + r;
            ull sfd = fdup2(sf);
#pragma unroll
            for (int dp = 0; dp < 4; dp++) acc2[i][dp] = fmul2(acc2[i][dp], sfd);
            int rl = ty * 4 + i;
            *reinterpret_cast<float4*>(&Ps[rl * ASTR + tx * 8]) =
                make_float4(s[i][0], s[i][1], s[i][2], s[i][3]);
            *reinterpret_cast<float4*>(&Ps[rl * ASTR + tx * 8 + 4]) =
                make_float4(s[i][4], s[i][5], s[i][6], s[i][7]);
        }
        __syncwarp();  // P rows ty*4+i live within the 8 tx lanes of this warp

        // acc += P @ V : V d-pairs natural, P broadcast + reg dup
#pragma unroll 4
        for (int jj2 = 0; jj2 < 32; jj2++) {
            int j = jj2 * 2;
            ulonglong2 vaA = *reinterpret_cast<const ulonglong2*>(&Vs[j * 64 + tx * 8]);
            ulonglong2 vaB = *reinterpret_cast<const ulonglong2*>(&Vs[j * 64 + tx * 8 + 4]);
            ulonglong2 vbA = *reinterpret_cast<const ulonglong2*>(&Vs[(j + 1) * 64 + tx * 8]);
            ulonglong2 vbB = *reinterpret_cast<const ulonglong2*>(&Vs[(j + 1) * 64 + tx * 8 + 4]);
            ull va[4] = {vaA.x, vaA.y, vaB.x, vaB.y};
            ull vb[4] = {vbA.x, vbA.y, vbB.x, vbB.y};
#pragma unroll
            for (int i = 0; i < 4; i++) {
                float2 pp = *reinterpret_cast<const float2*>(&Ps[(ty * 4 + i) * ASTR + j]);
                ull pa = fdup2(pp.x);
                ull pb = fdup2(pp.y);
#pragma unroll
                for (int dp = 0; dp < 4; dp++) {
                    acc2[i][dp] = ffma2(pa, va[dp], acc2[i][dp]);
                    acc2[i][dp] = ffma2(pb, vb[dp], acc2[i][dp]);
                }
            }
        }
    }

    // epilogue: normalize, write y[b][t][h*64 + d]
#pragma unroll
    for (int i = 0; i < 4; i++) {
        float inv_l = 1.0f / l[i];
        int row = i0 + ty * 4 + i;
        float a0, a1, a2, a3, a4, a5, a6, a7;
        funpack2(a0, a1, acc2[i][0]);
        funpack2(a2, a3, acc2[i][1]);
        funpack2(a4, a5, acc2[i][2]);
        funpack2(a6, a7, acc2[i][3]);
        float* Yp = Y + ((size_t)b * T_ + row) * D_ + h * HD_ + tx * 8;
        *reinterpret_cast<float4*>(Yp) =
            make_float4(a0 * inv_l, a1 * inv_l, a2 * inv_l, a3 * inv_l);
        *reinterpret_cast<float4*>(Yp + 4) =
            make_float4(a4 * inv_l, a5 * inv_l, a6 * inv_l, a7 * inv_l);
    }
}

// ---------------- launch ----------------
extern "C" void kernel_launch(void* const* d_in, const int* in_sizes, int n_in,
                              void* d_out, int out_size) {
    const float* x     = (const float*)d_in[0];
    const float* Wq    = (const float*)d_in[1];
    const float* Wk    = (const float*)d_in[2];
    const float* Wv    = (const float*)d_in[3];
    const float* Wproj = (const float*)d_in[4];
    const float* qg    = (const float*)d_in[5];
    const float* Aq    = (const float*)d_in[6];
    const float* Bq    = (const float*)d_in[7];
    const float* Av    = (const float*)d_in[8];
    const float* Bv    = (const float*)d_in[9];
    float* out = (float*)d_out;

    float *pWqe, *pWkv, *pq, *pkv, *pqh, *pkh, *pvh, *py;
    cudaGetSymbolAddress((void**)&pWqe, g_Wq_eff);
    cudaGetSymbolAddress((void**)&pWkv, g_Wkv);
    cudaGetSymbolAddress((void**)&pq, g_q);
    cudaGetSymbolAddress((void**)&pkv, g_kv);
    cudaGetSymbolAddress((void**)&pqh, g_qh);
    cudaGetSymbolAddress((void**)&pkh, g_kh);
    cudaGetSymbolAddress((void**)&pvh, g_vh);
    cudaGetSymbolAddress((void**)&py, g_y);

    // 1. fold LoRA / build combined weights
    lora_fuse<<<(D_ * D_) / 256, 256>>>(Wq, Bq, Aq, pWqe, D_, D_);
    build_wkv<<<(KV2_ * D_) / 256, 256>>>(Wk, Wv, Bv, Av, pWkv);

    // 2. projections (FFMA2 GEMM)
    dim3 gq(D_ / 128, (B_ * T_) / 128);
    dim3 gkv(KV2_ / 128, (B_ * T_) / 128);
    gemm_nt_f2<<<gq, 256>>>(x, pWqe, pq, B_ * T_, D_, D_);
    gemm_nt_f2<<<gkv, 256>>>(x, pWkv, pkv, B_ * T_, KV2_, D_);

    // 3. norm + rope + transpose
    q_prep<<<(B_ * T_ * NH_) / 8, 256>>>(pq, qg, pqh);
    kv_prep<<<(B_ * T_ * NKV_) / 8, 256>>>(pkv, pkh, pvh);

    // 4. attention (FFMA2 flash v3: 64x64, 4x8 microtile, 3 CTAs/SM)
    cudaFuncSetAttribute(attn_f3,
                         cudaFuncAttributeMaxDynamicSharedMemorySize, A_SMEM);
    dim3 ga(T_ / 64, B_ * NH_);
    attn_f3<<<ga, 128, A_SMEM>>>(pqh, pkh, pvh, py);

    // 5. output projection
    gemm_nt_f2<<<gq, 256>>>(py, Wproj, out, B_ * T_, D_, D_);
}

// round 13
// speedup vs baseline: 1.2260x; 1.1453x over previous
#include <cuda_runtime.h>
#include <cuda_bf16.h>
#include <math.h>

#define B_   2
#define T_   2048
#define D_   1024
#define NH_  16
#define NKV_ 4
#define HD_  64
#define KD_  256
#define KV2_ 512
#define FULLMASK 0xffffffffu

typedef unsigned long long ull;

// ---------------- f32x2 packed helpers (GEMM path) ----------------
__device__ __forceinline__ ull ffma2(ull a, ull b, ull c) {
    ull d;
    asm("fma.rn.f32x2 %0, %1, %2, %3;" : "=l"(d) : "l"(a), "l"(b), "l"(c));
    return d;
}
__device__ __forceinline__ ull fdup2(float x) {
    ull r;
    asm("mov.b64 %0, {%1, %1};" : "=l"(r) : "f"(x));
    return r;
}
__device__ __forceinline__ void funpack2(float& lo, float& hi, ull v) {
    asm("mov.b64 {%0, %1}, %2;" : "=f"(lo), "=f"(hi) : "l"(v));
}

// ---------------- bf16 mma helpers (attention path) ----------------
__device__ __forceinline__ void mma_bf16(float* d, const unsigned* a,
                                         const unsigned* b, const float* c) {
    asm volatile(
        "mma.sync.aligned.m16n8k16.row.col.f32.bf16.bf16.f32 "
        "{%0,%1,%2,%3}, {%4,%5,%6,%7}, {%8,%9}, {%10,%11,%12,%13};"
        : "=f"(d[0]), "=f"(d[1]), "=f"(d[2]), "=f"(d[3])
        : "r"(a[0]), "r"(a[1]), "r"(a[2]), "r"(a[3]),
          "r"(b[0]), "r"(b[1]),
          "f"(c[0]), "f"(c[1]), "f"(c[2]), "f"(c[3]));
}
// pack two f32 -> bf16x2 reg: lo -> low half, hi -> high half
__device__ __forceinline__ unsigned pack_bf16(float lo, float hi) {
    unsigned r;
    asm("cvt.rn.bf16x2.f32 %0, %1, %2;" : "=r"(r) : "f"(hi), "f"(lo));
    return r;
}
__device__ __forceinline__ float bf_lo_f32(unsigned p) {
    return __uint_as_float(p << 16);
}
__device__ __forceinline__ float bf_hi_f32(unsigned p) {
    return __uint_as_float(p & 0xFFFF0000u);
}

// ---------------- scratch (device globals; no runtime alloc) ----------------
__device__ float g_Wq_eff[D_ * D_];
__device__ float g_Wkv[KV2_ * D_];            // rows 0..255 = Wk, 256..511 = Wv_eff
__device__ float g_q[B_ * T_ * D_];           // pre-norm q (fp32)
__device__ float g_kv[B_ * T_ * KV2_];        // (k | v) fp32
__device__ float g_y[B_ * T_ * D_];           // attention output
__device__ __nv_bfloat16 g_qhi[B_ * NH_ * T_ * HD_];   // [b][h][t][d]
__device__ __nv_bfloat16 g_qlo[B_ * NH_ * T_ * HD_];
__device__ __nv_bfloat16 g_khi[B_ * NKV_ * T_ * HD_];  // [b][kvh][t][d]
__device__ __nv_bfloat16 g_klo[B_ * NKV_ * T_ * HD_];
__device__ __nv_bfloat16 g_vthi[B_ * NKV_ * HD_ * T_]; // [b][kvh][d][t]  TRANSPOSED
__device__ __nv_bfloat16 g_vtlo[B_ * NKV_ * HD_ * T_];

// ---------------- Wq_eff = Wq + Bq @ Aq ----------------
__global__ __launch_bounds__(256) void lora_fuse(
    const float* __restrict__ W, const float* __restrict__ Bm,
    const float* __restrict__ Am, float* __restrict__ Weff, int N, int K) {
    int idx = blockIdx.x * 256 + threadIdx.x;
    if (idx >= N * K) return;
    int n = idx / K, k = idx - n * K;
    float acc = W[idx];
#pragma unroll
    for (int r = 0; r < 8; r++) acc += Bm[n * 8 + r] * Am[r * K + k];
    Weff[idx] = acc;
}

__global__ __launch_bounds__(256) void build_wkv(
    const float* __restrict__ Wk, const float* __restrict__ Wv,
    const float* __restrict__ Bv, const float* __restrict__ Av,
    float* __restrict__ Wkv) {
    int idx = blockIdx.x * 256 + threadIdx.x;
    if (idx >= KV2_ * D_) return;
    int n = idx >> 10, k = idx & 1023;
    if (n < KD_) {
        Wkv[idx] = Wk[n * D_ + k];
    } else {
        int nv = n - KD_;
        float acc = Wv[nv * D_ + k];
#pragma unroll
        for (int r = 0; r < 8; r++) acc += Bv[nv * 8 + r] * Av[r * D_ + k];
        Wkv[idx] = acc;
    }
}

// ---------------- C[M,N] = A[M,K] @ B[N,K]^T, fp32 via FFMA2 (unchanged) ----
__global__ __launch_bounds__(256, 2) void gemm_nt_f2(
    const float* __restrict__ A, const float* __restrict__ B,
    float* __restrict__ C, int M, int N, int K) {
    __shared__ float As[16 * 128];
    __shared__ float Bs[16 * 128];
    int tid = threadIdx.x;
    int tx = tid & 15, ty = tid >> 4;
    const float* Ab = A + (size_t)(blockIdx.y * 128) * K;
    const float* Bb = B + (size_t)(blockIdx.x * 128) * K;
    int lr = tid >> 2;
    int lc = (tid & 3) << 2;

    ull acc[8][4];
#pragma unroll
    for (int i = 0; i < 8; i++)
#pragma unroll
        for (int j = 0; j < 4; j++) acc[i][j] = 0ull;

    float4 av0 = *reinterpret_cast<const float4*>(Ab + (size_t)lr * K + lc);
    float4 av1 = *reinterpret_cast<const float4*>(Ab + (size_t)(lr + 64) * K + lc);
    float4 bv0 = *reinterpret_cast<const float4*>(Bb + (size_t)lr * K + lc);
    float4 bv1 = *reinterpret_cast<const float4*>(Bb + (size_t)(lr + 64) * K + lc);

    for (int k0 = 0; k0 < K; k0 += 16) {
        __syncthreads();
        {
            float a0[4] = {av0.x, av0.y, av0.z, av0.w};
            float a1[4] = {av1.x, av1.y, av1.z, av1.w};
            float b0[4] = {bv0.x, bv0.y, bv0.z, bv0.w};
            float b1[4] = {bv1.x, bv1.y, bv1.z, bv1.w};
#pragma unroll
            for (int c = 0; c < 4; c++) {
                As[(lc + c) * 128 + lr]      = a0[c];
                As[(lc + c) * 128 + lr + 64] = a1[c];
                Bs[(lc + c) * 128 + lr]      = b0[c];
                Bs[(lc + c) * 128 + lr + 64] = b1[c];
            }
        }
        __syncthreads();
        if (k0 + 16 < K) {
            av0 = *reinterpret_cast<const float4*>(Ab + (size_t)lr * K + k0 + 16 + lc);
            av1 = *reinterpret_cast<const float4*>(Ab + (size_t)(lr + 64) * K + k0 + 16 + lc);
            bv0 = *reinterpret_cast<const float4*>(Bb + (size_t)lr * K + k0 + 16 + lc);
            bv1 = *reinterpret_cast<const float4*>(Bb + (size_t)(lr + 64) * K + k0 + 16 + lc);
        }
#pragma unroll
        for (int kk = 0; kk < 16; kk++) {
            float4 a0 = *reinterpret_cast<const float4*>(&As[kk * 128 + ty * 4]);
            float4 a1 = *reinterpret_cast<const float4*>(&As[kk * 128 + 64 + ty * 4]);
            ulonglong2 b0 = *reinterpret_cast<const ulonglong2*>(&Bs[kk * 128 + tx * 4]);
            ulonglong2 b1 = *reinterpret_cast<const ulonglong2*>(&Bs[kk * 128 + 64 + tx * 4]);
            ull bb[4] = {b0.x, b0.y, b1.x, b1.y};
            float av[8] = {a0.x, a0.y, a0.z, a0.w, a1.x, a1.y, a1.z, a1.w};
#pragma unroll
            for (int i = 0; i < 8; i++) {
                ull ai = fdup2(av[i]);
#pragma unroll
                for (int j = 0; j < 4; j++) acc[i][j] = ffma2(ai, bb[j], acc[i][j]);
            }
        }
    }

#pragma unroll
    for (int i = 0; i < 8; i++) {
        int rloc = (i < 4) ? (ty * 4 + i) : (64 + ty * 4 + i - 4);
        size_t row = (size_t)blockIdx.y * 128 + rloc;
        float c0, c1, c2, c3, c4, c5, c6, c7;
        funpack2(c0, c1, acc[i][0]);
        funpack2(c2, c3, acc[i][1]);
        funpack2(c4, c5, acc[i][2]);
        funpack2(c6, c7, acc[i][3]);
        float* Cp = C + row * N + blockIdx.x * 128;
        *reinterpret_cast<float4*>(Cp + tx * 4)      = make_float4(c0, c1, c2, c3);
        *reinterpret_cast<float4*>(Cp + 64 + tx * 4) = make_float4(c4, c5, c6, c7);
    }
}

// ---------------- RoPE / norm ----------------
__device__ __forceinline__ void rope_cs(int t, int j, float& c, float& s) {
    float e = (2.0f * (float)j) / 16.0f;
    float inv = 1.0f / powf(10000.0f, e);
    float f = (float)t * inv;
    c = cosf(f);
    s = sinf(f);
}

__device__ __forceinline__ void norm_rope_vals(
    const float* __restrict__ src, int t, float scale, int lane,
    float& o0, float& o1) {
    float2 v = *reinterpret_cast<const float2*>(src + lane * 2);
    float ss = v.x * v.x + v.y * v.y;
#pragma unroll
    for (int o = 16; o; o >>= 1) ss += __shfl_xor_sync(FULLMASK, ss, o);
    float rms = rsqrtf(ss * (1.0f / 64.0f) + 1.1920929e-7f);
    float v0 = v.x * rms, v1 = v.y * rms;
    float u0 = __shfl_xor_sync(FULLMASK, v0, 4);
    float u1 = __shfl_xor_sync(FULLMASK, v1, 4);
    int d0 = lane * 2;
    if (d0 < 8) {
        float c0, s0, c1, s1;
        rope_cs(t, d0, c0, s0);
        rope_cs(t, d0 + 1, c1, s1);
        v0 = v0 * c0 + u0 * s0;
        v1 = v1 * c1 + u1 * s1;
    } else if (d0 < 16) {
        float c0, s0, c1, s1;
        rope_cs(t, d0 - 8, c0, s0);
        rope_cs(t, d0 - 7, c1, s1);
        v0 = -v0 * c0 + u0 * s0;
        v1 = -v1 * c1 + u1 * s1;
    }
    o0 = v0 * scale;
    o1 = v1 * scale;
}

__device__ __forceinline__ void store_split(
    __nv_bfloat16* hi, __nv_bfloat16* lo, size_t off, float v0, float v1) {
    __nv_bfloat16 h0 = __float2bfloat16(v0), h1 = __float2bfloat16(v1);
    __nv_bfloat162 hp; hp.x = h0; hp.y = h1;
    __nv_bfloat162 lp;
    lp.x = __float2bfloat16(v0 - __bfloat162float(h0));
    lp.y = __float2bfloat16(v1 - __bfloat162float(h1));
    *reinterpret_cast<__nv_bfloat162*>(hi + off) = hp;
    *reinterpret_cast<__nv_bfloat162*>(lo + off) = lp;
}

// q: rms+rope+gain*scale, split-bf16, transpose to [b][h][t][d]
__global__ __launch_bounds__(256) void q_prep_b(
    const float* __restrict__ Qin, const float* __restrict__ qgain,
    __nv_bfloat16* __restrict__ Qhi, __nv_bfloat16* __restrict__ Qlo) {
    int warp = (blockIdx.x * 256 + threadIdx.x) >> 5;
    int lane = threadIdx.x & 31;
    if (warp >= B_ * T_ * NH_) return;
    int h = warp & 15;
    int t = (warp >> 4) & 2047;
    int b = warp >> 15;
    const float* src = Qin + ((size_t)(b * T_ + t)) * D_ + h * HD_;
    float scale = qgain[h] * 0.125f;
    float v0, v1;
    norm_rope_vals(src, t, scale, lane, v0, v1);
    size_t off = (((size_t)(b * NH_ + h)) * T_ + t) * HD_ + lane * 2;
    store_split(Qhi, Qlo, off, v0, v1);
}

// k: rms+rope, split-bf16, [b][kvh][t][d]
__global__ __launch_bounds__(256) void k_prep_b(
    const float* __restrict__ KVin,
    __nv_bfloat16* __restrict__ Khi, __nv_bfloat16* __restrict__ Klo) {
    int warp = (blockIdx.x * 256 + threadIdx.x) >> 5;
    int lane = threadIdx.x & 31;
    if (warp >= B_ * T_ * NKV_) return;
    int hk = warp & 3;
    int t = (warp >> 2) & 2047;
    int b = warp >> 13;
    const float* src = KVin + ((size_t)(b * T_ + t)) * KV2_ + hk * HD_;
    float v0, v1;
    norm_rope_vals(src, t, 1.0f, lane, v0, v1);
    size_t off = (((size_t)(b * NKV_ + hk)) * T_ + t) * HD_ + lane * 2;
    store_split(Khi, Klo, off, v0, v1);
}

// v: split-bf16, TRANSPOSED to [b][kvh][d][t] via smem tile
__global__ __launch_bounds__(256) void v_trans(
    const float* __restrict__ KVin,
    __nv_bfloat16* __restrict__ Vthi, __nv_bfloat16* __restrict__ Vtlo) {
    __shared__ float ts[64][65];
    int t0 = blockIdx.x * 64;
    int bk = blockIdx.y;            // b*NKV + kvh
    int b = bk >> 2, kvh = bk & 3;
#pragma unroll
    for (int it = 0; it < 4; it++) {
        int idx = threadIdx.x + it * 256;   // float4 index 0..1023
        int t = idx >> 4, d4 = (idx & 15) << 2;
        float4 v = *reinterpret_cast<const float4*>(
            &KVin[((size_t)b * T_ + t0 + t) * KV2_ + KD_ + kvh * HD_ + d4]);
        ts[t][d4] = v.x; ts[t][d4 + 1] = v.y;
        ts[t][d4 + 2] = v.z; ts[t][d4 + 3] = v.w;
    }
    __syncthreads();
#pragma unroll
    for (int it = 0; it < 8; it++) {
        int idx = threadIdx.x + it * 256;   // pair index 0..2047
        int d = idx >> 5, tp = (idx & 31) << 1;
        float v0 = ts[tp][d], v1 = ts[tp + 1][d];
        size_t off = ((size_t)bk * HD_ + d) * T_ + t0 + tp;
        store_split(Vthi, Vtlo, off, v0, v1);
    }
}

// ---------------- causal flash attention: bf16-split mma.sync ----------------
// 64q x 64k tile, 128 threads (4 warps x 16 rows). hi/lo split: 3 mma terms.
// smem (bf16, stride 72): Ksh | Ksl | Vsh | Vsl = 36864B. Q staged in Ksh/Ksl.
#define XSTR 72
#define ATT_SMEM (4 * 64 * XSTR * 2)
__global__ __launch_bounds__(128, 3) void attn_mma(
    const __nv_bfloat16* __restrict__ Qhi, const __nv_bfloat16* __restrict__ Qlo,
    const __nv_bfloat16* __restrict__ Khi, const __nv_bfloat16* __restrict__ Klo,
    const __nv_bfloat16* __restrict__ Vthi, const __nv_bfloat16* __restrict__ Vtlo,
    float* __restrict__ Y) {
    extern __shared__ __nv_bfloat16 smh[];
    __nv_bfloat16* Ksh = smh;
    __nv_bfloat16* Ksl = smh + 64 * XSTR;
    __nv_bfloat16* Vsh = smh + 2 * 64 * XSTR;
    __nv_bfloat16* Vsl = smh + 3 * 64 * XSTR;
    int tid = threadIdx.x;
    int lane = tid & 31, w = tid >> 5;
    int g = lane >> 2, i2 = (lane & 3) << 1;
    int bh = blockIdx.y, b = bh >> 4, h = bh & 15;
    int qt = (int)gridDim.x - 1 - (int)blockIdx.x;   // reversed for balance
    int i0 = qt * 64;
    int kvh = h >> 2;
    size_t qbase = ((size_t)(b * NH_ + h) * T_ + i0) * HD_;
    size_t kbase = (size_t)(b * NKV_ + kvh) * T_ * HD_;
    size_t vtbase = (size_t)(b * NKV_ + kvh) * HD_ * T_;

    // ---- stage Q (hi->Ksh, lo->Ksl), read A-fragments to registers ----
#pragma unroll
    for (int it = 0; it < 8; it++) {
        int idx = tid + it * 128;
        int mat = idx >> 9, r = (idx >> 3) & 63, c = idx & 7;
        const __nv_bfloat16* src = (mat ? Qlo : Qhi) + qbase + r * HD_ + c * 8;
        __nv_bfloat16* dst = (mat ? Ksl : Ksh) + r * XSTR + c * 8;
        *reinterpret_cast<uint4*>(dst) = *reinterpret_cast<const uint4*>(src);
    }
    __syncthreads();
    unsigned qa_h[4][4], qa_l[4][4];
    int qr = w * 16 + g;
#pragma unroll
    for (int kk = 0; kk < 4; kk++) {
        qa_h[kk][0] = *reinterpret_cast<unsigned*>(&Ksh[qr * XSTR + kk * 16 + i2]);
        qa_h[kk][1] = *reinterpret_cast<unsigned*>(&Ksh[(qr + 8) * XSTR + kk * 16 + i2]);
        qa_h[kk][2] = *reinterpret_cast<unsigned*>(&Ksh[qr * XSTR + kk * 16 + 8 + i2]);
        qa_h[kk][3] = *reinterpret_cast<unsigned*>(&Ksh[(qr + 8) * XSTR + kk * 16 + 8 + i2]);
        qa_l[kk][0] = *reinterpret_cast<unsigned*>(&Ksl[qr * XSTR + kk * 16 + i2]);
        qa_l[kk][1] = *reinterpret_cast<unsigned*>(&Ksl[(qr + 8) * XSTR + kk * 16 + i2]);
        qa_l[kk][2] = *reinterpret_cast<unsigned*>(&Ksl[qr * XSTR + kk * 16 + 8 + i2]);
        qa_l[kk][3] = *reinterpret_cast<unsigned*>(&Ksl[(qr + 8) * XSTR + kk * 16 + 8 + i2]);
    }

    float m0 = -1e30f, m1 = -1e30f, l0 = 0.f, l1 = 0.f;
    float yac[8][4];
#pragma unroll
    for (int nt = 0; nt < 8; nt++)
#pragma unroll
        for (int j = 0; j < 4; j++) yac[nt][j] = 0.f;

    for (int kt = 0; kt <= qt; kt++) {
        int j0 = kt * 64;
        __syncthreads();   // protects Q-frag reads (iter 0) and prior-iter smem
#pragma unroll
        for (int it = 0; it < 16; it++) {
            int idx = tid + it * 128;
            int mat = idx >> 9, r = (idx >> 3) & 63, c = idx & 7;
            const __nv_bfloat16* src;
            if (mat == 0)      src = Khi + kbase + (size_t)(j0 + r) * HD_ + c * 8;
            else if (mat == 1) src = Klo + kbase + (size_t)(j0 + r) * HD_ + c * 8;
            else if (mat == 2) src = Vthi + vtbase + (size_t)r * T_ + j0 + c * 8;
            else               src = Vtlo + vtbase + (size_t)r * T_ + j0 + c * 8;
            *reinterpret_cast<uint4*>(smh + mat * 64 * XSTR + r * XSTR + c * 8) =
                *reinterpret_cast<const uint4*>(src);
        }
        __syncthreads();

        // ---- S = Q K^T (3-term split) ----
        float s[8][4];
#pragma unroll
        for (int nt = 0; nt < 8; nt++)
#pragma unroll
            for (int j = 0; j < 4; j++) s[nt][j] = 0.f;
#pragma unroll
        for (int kk = 0; kk < 4; kk++) {
#pragma unroll
            for (int nt = 0; nt < 8; nt++) {
                int roff = (nt * 8 + g) * XSTR + kk * 16 + i2;
                unsigned bh_[2], bl_[2];
                bh_[0] = *reinterpret_cast<unsigned*>(&Ksh[roff]);
                bh_[1] = *reinterpret_cast<unsigned*>(&Ksh[roff + 8]);
                bl_[0] = *reinterpret_cast<unsigned*>(&Ksl[roff]);
                bl_[1] = *reinterpret_cast<unsigned*>(&Ksl[roff + 8]);
                mma_bf16(s[nt], qa_h[kk], bh_, s[nt]);
                mma_bf16(s[nt], qa_h[kk], bl_, s[nt]);
                mma_bf16(s[nt], qa_l[kk], bh_, s[nt]);
            }
        }

        if (kt == qt) {  // diagonal tile: mask col > row (local indices, j0==i0)
#pragma unroll
            for (int nt = 0; nt < 8; nt++) {
                int c0 = nt * 8 + i2;
                if (c0 > qr)         s[nt][0] = -1e30f;
                if (c0 + 1 > qr)     s[nt][1] = -1e30f;
                if (c0 > qr + 8)     s[nt][2] = -1e30f;
                if (c0 + 1 > qr + 8) s[nt][3] = -1e30f;
            }
        }

        // ---- online softmax (rows qr, qr+8; reduce over quad lanes) ----
        float t0 = -1e30f, t1 = -1e30f;
#pragma unroll
        for (int nt = 0; nt < 8; nt++) {
            t0 = fmaxf(t0, fmaxf(s[nt][0], s[nt][1]));
            t1 = fmaxf(t1, fmaxf(s[nt][2], s[nt][3]));
        }
        t0 = fmaxf(t0, __shfl_xor_sync(FULLMASK, t0, 1));
        t0 = fmaxf(t0, __shfl_xor_sync(FULLMASK, t0, 2));
        t1 = fmaxf(t1, __shfl_xor_sync(FULLMASK, t1, 1));
        t1 = fmaxf(t1, __shfl_xor_sync(FULLMASK, t1, 2));
        float mn0 = fmaxf(m0, t0), mn1 = fmaxf(m1, t1);
        float sf0 = __expf(m0 - mn0), sf1 = __expf(m1 - mn1);
        m0 = mn0; m1 = mn1;
        float r0 = 0.f, r1 = 0.f;
#pragma unroll
        for (int nt = 0; nt < 8; nt++) {
            s[nt][0] = __expf(s[nt][0] - mn0);
            s[nt][1] = __expf(s[nt][1] - mn0);
            s[nt][2] = __expf(s[nt][2] - mn1);
            s[nt][3] = __expf(s[nt][3] - mn1);
            r0 += s[nt][0] + s[nt][1];
            r1 += s[nt][2] + s[nt][3];
        }
        r0 += __shfl_xor_sync(FULLMASK, r0, 1);
        r0 += __shfl_xor_sync(FULLMASK, r0, 2);
        r1 += __shfl_xor_sync(FULLMASK, r1, 1);
        r1 += __shfl_xor_sync(FULLMASK, r1, 2);
        l0 = l0 * sf0 + r0;
        l1 = l1 * sf1 + r1;
#pragma unroll
        for (int nt = 0; nt < 8; nt++) {
            yac[nt][0] *= sf0; yac[nt][1] *= sf0;
            yac[nt][2] *= sf1; yac[nt][3] *= sf1;
        }

        // ---- PV: pack P (hi/lo), acc += P @ V (3-term split) ----
#pragma unroll
        for (int kk = 0; kk < 4; kk++) {
            int n0 = 2 * kk, n1 = 2 * kk + 1;
            unsigned pah[4], pal[4];
            pah[0] = pack_bf16(s[n0][0], s[n0][1]);
            pah[1] = pack_bf16(s[n0][2], s[n0][3]);
            pah[2] = pack_bf16(s[n1][0], s[n1][1]);
            pah[3] = pack_bf16(s[n1][2], s[n1][3]);
            pal[0] = pack_bf16(s[n0][0] - bf_lo_f32(pah[0]),
                               s[n0][1] - bf_hi_f32(pah[0]));
            pal[1] = pack_bf16(s[n0][2] - bf_lo_f32(pah[1]),
                               s[n0][3] - bf_hi_f32(pah[1]));
            pal[2] = pack_bf16(s[n1][0] - bf_lo_f32(pah[2]),
                               s[n1][1] - bf_hi_f32(pah[2]));
            pal[3] = pack_bf16(s[n1][2] - bf_lo_f32(pah[3]),
                               s[n1][3] - bf_hi_f32(pah[3]));
#pragma unroll
            for (int nt = 0; nt < 8; nt++) {
                int roff = (nt * 8 + g) * XSTR + kk * 16 + i2;
                unsigned vh_[2], vl_[2];
                vh_[0] = *reinterpret_cast<unsigned*>(&Vsh[roff]);
                vh_[1] = *reinterpret_cast<unsigned*>(&Vsh[roff + 8]);
                vl_[0] = *reinterpret_cast<unsigned*>(&Vsl[roff]);
                vl_[1] = *reinterpret_cast<unsigned*>(&Vsl[roff + 8]);
                mma_bf16(yac[nt], pah, vh_, yac[nt]);
                mma_bf16(yac[nt], pah, vl_, yac[nt]);
                mma_bf16(yac[nt], pal, vh_, yac[nt]);
            }
        }
    }

    // ---- epilogue ----
    float inv0 = 1.0f / l0, inv1 = 1.0f / l1;
    float* Y0 = Y + ((size_t)b * T_ + i0 + qr) * D_ + h * HD_;
    float* Y1 = Y0 + 8 * D_;
#pragma unroll
    for (int nt = 0; nt < 8; nt++) {
        *reinterpret_cast<float2*>(Y0 + nt * 8 + i2) =
            make_float2(yac[nt][0] * inv0, yac[nt][1] * inv0);
        *reinterpret_cast<float2*>(Y1 + nt * 8 + i2) =
            make_float2(yac[nt][2] * inv1, yac[nt][3] * inv1);
    }
}

// ---------------- launch ----------------
extern "C" void kernel_launch(void* const* d_in, const int* in_sizes, int n_in,
                              void* d_out, int out_size) {
    const float* x     = (const float*)d_in[0];
    const float* Wq    = (const float*)d_in[1];
    const float* Wk    = (const float*)d_in[2];
    const float* Wv    = (const float*)d_in[3];
    const float* Wproj = (const float*)d_in[4];
    const float* qg    = (const float*)d_in[5];
    const float* Aq    = (const float*)d_in[6];
    const float* Bq    = (const float*)d_in[7];
    const float* Av    = (const float*)d_in[8];
    const float* Bv    = (const float*)d_in[9];
    float* out = (float*)d_out;

    float *pWqe, *pWkv, *pq, *pkv, *py;
    __nv_bfloat16 *pqhi, *pqlo, *pkhi, *pklo, *pvthi, *pvtlo;
    cudaGetSymbolAddress((void**)&pWqe, g_Wq_eff);
    cudaGetSymbolAddress((void**)&pWkv, g_Wkv);
    cudaGetSymbolAddress((void**)&pq, g_q);
    cudaGetSymbolAddress((void**)&pkv, g_kv);
    cudaGetSymbolAddress((void**)&py, g_y);
    cudaGetSymbolAddress((void**)&pqhi, g_qhi);
    cudaGetSymbolAddress((void**)&pqlo, g_qlo);
    cudaGetSymbolAddress((void**)&pkhi, g_khi);
    cudaGetSymbolAddress((void**)&pklo, g_klo);
    cudaGetSymbolAddress((void**)&pvthi, g_vthi);
    cudaGetSymbolAddress((void**)&pvtlo, g_vtlo);

    // 1. fold LoRA / build combined weights
    lora_fuse<<<(D_ * D_) / 256, 256>>>(Wq, Bq, Aq, pWqe, D_, D_);
    build_wkv<<<(KV2_ * D_) / 256, 256>>>(Wk, Wv, Bv, Av, pWkv);

    // 2. projections (FFMA2 GEMM)
    dim3 gq(D_ / 128, (B_ * T_) / 128);
    dim3 gkv(KV2_ / 128, (B_ * T_) / 128);
    gemm_nt_f2<<<gq, 256>>>(x, pWqe, pq, B_ * T_, D_, D_);
    gemm_nt_f2<<<gkv, 256>>>(x, pWkv, pkv, B_ * T_, KV2_, D_);

    // 3. norm + rope + bf16 hi/lo split (+ V transpose)
    q_prep_b<<<(B_ * T_ * NH_) / 8, 256>>>(pq, qg, pqhi, pqlo);
    k_prep_b<<<(B_ * T_ * NKV_) / 8, 256>>>(pkv, pkhi, pklo);
    v_trans<<<dim3(T_ / 64, B_ * NKV_), 256>>>(pkv, pvthi, pvtlo);

    // 4. attention (bf16-split tensor-core flash)
    dim3 ga(T_ / 64, B_ * NH_);
    attn_mma<<<ga, 128, ATT_SMEM>>>(pqhi, pqlo, pkhi, pklo, pvthi, pvtlo, py);

    // 5. output projection
    gemm_nt_f2<<<gq, 256>>>(py, Wproj, out, B_ * T_, D_, D_);
}